// round 12
// baseline (speedup 1.0000x reference)
#include <cuda_runtime.h>
#include <cuda_bf16.h>
#include <cstdint>

// Fused SelfAttention, fully tensor-core (HMMA mma.sync bf16, 3-term split).
// E=128, S=32, H=4, D=32. CTA = 64 rows (2 batches), 256 threads, grid 8192.
// Warp w -> tile (m0=(w>>2)*32, n0=(w&3)*32) == attention block (batch, head).
// R11: back to 64-row CTAs with register-resident attention (R10) so that
// smem = A(32K)+W(64K)+LN(2K) = 98KB -> 2 CTAs/SM; independent CTAs stagger
// phases, covering each other's fills/softmax/epilogue with gemm work.
//
// SMEM:
//   A @0     : bf16 [64][256] (hi|lo), 512B rows, 16B-chunk xor swizzle. 32KB
//   W @32768 : bf16 [128][256] swizzled weight image (one of Wq/Wk/Wv/Wo). 64KB
//   LN partials @98304 : float2[64][4]. 2KB

typedef unsigned int u32;

#define NT 256
#define AOFF 0
#define WOFF 32768
#define POFF 98304
#define SMEM_BYTES 100352
#define QSCALE 0.17677669529663687f

__device__ __align__(16) unsigned char g_Wpk[262144];

// ---------------- prep: split W into bf16 hi/lo swizzled smem images ----------
__global__ void prep_split(const float* __restrict__ Wq, const float* __restrict__ Wk,
                           const float* __restrict__ Wv, const float* __restrict__ Wo) {
    int id = blockIdx.x * blockDim.x + threadIdx.x;   // u32 words
    const float* W = (id < 16384) ? Wq : (id < 32768) ? Wk : (id < 49152) ? Wv : Wo;
    int rem = id & 16383;
    int f = rem >> 7;
    int w = rem & 127;
    int pc = w >> 2, j = w & 3;
    int lc = pc ^ (f & 7);
    int k0 = lc * 8 + j * 2;
    __nv_bfloat16 v[2];
#pragma unroll
    for (int i = 0; i < 2; ++i) {
        int kc = k0 + i;
        if (kc < 128) {
            v[i] = __float2bfloat16_rn(W[f * 128 + kc]);
        } else {
            float x = W[f * 128 + (kc - 128)];
            __nv_bfloat16 h = __float2bfloat16_rn(x);
            v[i] = __float2bfloat16_rn(x - __bfloat162float(h));
        }
    }
    __nv_bfloat162 p = __halves2bfloat162(v[0], v[1]);
    ((u32*)g_Wpk)[id] = *(u32*)&p;
}

// ---------------- helpers ----------------
__device__ __forceinline__ u32 s2u(const void* p) {
    u32 a;
    asm("{ .reg .u64 t; cvta.to.shared.u64 t, %1; cvt.u32.u64 %0, t; }" : "=r"(a) : "l"(p));
    return a;
}
__device__ __forceinline__ void ldsm4(u32* r, u32 a) {
    asm volatile("ldmatrix.sync.aligned.m8n8.x4.shared.b16 {%0,%1,%2,%3}, [%4];"
                 : "=r"(r[0]), "=r"(r[1]), "=r"(r[2]), "=r"(r[3]) : "r"(a));
}
__device__ __forceinline__ u32 movm_t(u32 s) {
    u32 d;
    asm("movmatrix.sync.aligned.m8n8.trans.b16 %0, %1;" : "=r"(d) : "r"(s));
    return d;
}
__device__ __forceinline__ void mma16816(float* c, const u32* a, u32 b0, u32 b1) {
    asm volatile(
        "mma.sync.aligned.m16n8k16.row.col.f32.bf16.bf16.f32 "
        "{%0,%1,%2,%3}, {%4,%5,%6,%7}, {%8,%9}, {%0,%1,%2,%3};"
        : "+f"(c[0]), "+f"(c[1]), "+f"(c[2]), "+f"(c[3])
        : "r"(a[0]), "r"(a[1]), "r"(a[2]), "r"(a[3]), "r"(b0), "r"(b1));
}
__device__ __forceinline__ u32 pkbf(float a, float b) {
    __nv_bfloat162 t = __halves2bfloat162(__float2bfloat16_rn(a), __float2bfloat16_rn(b));
    return *(u32*)&t;
}
__device__ __forceinline__ u32 pkbf_lo(float a, float b, u32 hi) {
    __nv_bfloat162 h = *(__nv_bfloat162*)&hi;
    return pkbf(a - __bfloat162float(h.x), b - __bfloat162float(h.y));
}

// C[m0:+32][n0:+32] = A(64x128 hi/lo) @ W^T(128x128 hi/lo), 3-term split.
__device__ __forceinline__ void gemm32(u32 smA, u32 smW, int m0, int n0, int lane,
                                       float acc[2][4][4]) {
    u32 aRow[2]; int asw[2];
#pragma unroll
    for (int mt = 0; mt < 2; ++mt) {
        int ar = m0 + mt * 16 + (lane & 7) + ((lane & 8) ? 8 : 0);
        aRow[mt] = smA + ar * 512; asw[mt] = ar & 7;
    }
    const int acs = lane >> 4;
    u32 bRow[2]; int bsw[2];
#pragma unroll
    for (int ng = 0; ng < 2; ++ng) {
        int br = n0 + ng * 16 + (lane & 7) + ((lane & 16) ? 8 : 0);
        bRow[ng] = smW + br * 512; bsw[ng] = br & 7;
    }
    const int bcs = (lane >> 3) & 1;
#pragma unroll
    for (int mt = 0; mt < 2; ++mt)
#pragma unroll
        for (int nf = 0; nf < 4; ++nf)
#pragma unroll
            for (int c = 0; c < 4; ++c) acc[mt][nf][c] = 0.f;

#pragma unroll
    for (int j = 0; j < 8; ++j) {
        const int ach = 2 * j + acs, bch = 2 * j + bcs;
        u32 ah[2][4], al[2][4], bh[2][4], bl[2][4];
#pragma unroll
        for (int mt = 0; mt < 2; ++mt) {
            ldsm4(ah[mt], aRow[mt] + ((ach ^ asw[mt]) << 4));
            ldsm4(al[mt], aRow[mt] + (((16 + ach) ^ asw[mt]) << 4));
        }
#pragma unroll
        for (int ng = 0; ng < 2; ++ng) {
            ldsm4(bh[ng], bRow[ng] + ((bch ^ bsw[ng]) << 4));
            ldsm4(bl[ng], bRow[ng] + (((16 + bch) ^ bsw[ng]) << 4));
        }
#pragma unroll
        for (int mt = 0; mt < 2; ++mt)
#pragma unroll
            for (int ng = 0; ng < 2; ++ng) {
                mma16816(acc[mt][2 * ng],     ah[mt], bh[ng][0], bh[ng][1]);
                mma16816(acc[mt][2 * ng + 1], ah[mt], bh[ng][2], bh[ng][3]);
            }
#pragma unroll
        for (int mt = 0; mt < 2; ++mt)
#pragma unroll
            for (int ng = 0; ng < 2; ++ng) {
                mma16816(acc[mt][2 * ng],     al[mt], bh[ng][0], bh[ng][1]);
                mma16816(acc[mt][2 * ng + 1], al[mt], bh[ng][2], bh[ng][3]);
            }
#pragma unroll
        for (int mt = 0; mt < 2; ++mt)
#pragma unroll
            for (int ng = 0; ng < 2; ++ng) {
                mma16816(acc[mt][2 * ng],     ah[mt], bl[ng][0], bl[ng][1]);
                mma16816(acc[mt][2 * ng + 1], ah[mt], bl[ng][2], bl[ng][3]);
            }
    }
}

// c-frags -> bf16 hi/lo into the A-style [64][256] image (ctx writeback).
__device__ __forceinline__ void store_split(char* dst, const float acc[2][4][4],
                                            int m0, int n0, int lane) {
#pragma unroll
    for (int mt = 0; mt < 2; ++mt) {
        int r = m0 + mt * 16 + (lane >> 2);
        char* row0 = dst + r * 512;
        char* row1 = dst + (r + 8) * 512;
        int sw = r & 7;
#pragma unroll
        for (int nf = 0; nf < 4; ++nf) {
            int c = n0 + nf * 8 + 2 * (lane & 3);
            float v0 = acc[mt][nf][0], v1 = acc[mt][nf][1];
            float v2 = acc[mt][nf][2], v3 = acc[mt][nf][3];
            u32 h01 = pkbf(v0, v1), l01 = pkbf_lo(v0, v1, h01);
            u32 h23 = pkbf(v2, v3), l23 = pkbf_lo(v2, v3, h23);
            int ch = c >> 3, bo_ = (c & 7) * 2;
            *(u32*)(row0 + ((ch ^ sw) << 4) + bo_) = h01;
            *(u32*)(row0 + (((16 + ch) ^ sw) << 4) + bo_) = l01;
            *(u32*)(row1 + ((ch ^ sw) << 4) + bo_) = h23;
            *(u32*)(row1 + (((16 + ch) ^ sw) << 4) + bo_) = l23;
        }
    }
}

__device__ __forceinline__ void fillW(char* dstW, int g, int tid) {
    const uint4* src = (const uint4*)g_Wpk + g * 4096;
    uint4* dst = (uint4*)dstW;
#pragma unroll
    for (int p = 0; p < 16; ++p) dst[p * NT + tid] = __ldg(src + p * NT + tid);
}

// ---------------- main kernel ----------------
__global__ void __launch_bounds__(NT, 2)
fused_attn_fa(const float* __restrict__ inputs,
              const float* __restrict__ bq, const float* __restrict__ bk,
              const float* __restrict__ bv, const float* __restrict__ bo,
              const float* __restrict__ gamma, const float* __restrict__ beta,
              float* __restrict__ outp)
{
    extern __shared__ char sm[];
    const int tid = threadIdx.x;
    const int lane = tid & 31;
    const int warp = tid >> 5;
    const u32 smb = s2u(sm);
    const u32 smA = smb + AOFF, smW = smb + WOFF;
    const int m0 = (warp >> 2) * 32;    // batch block (rows): 0 or 32
    const int n0 = (warp & 3) * 32;     // head block (cols)
    const int h = warp & 3;
    const size_t tbase = (size_t)blockIdx.x * 8192;

    // ---- fill A (x split hi/lo) + Wq ----
    {
        const float4* gx = (const float4*)(inputs + tbase);
#pragma unroll
        for (int p = 0; p < 8; ++p) {
            int e = p * NT + tid;
            int row = e >> 5, c4 = e & 31;
            float4 v = __ldg(gx + e);
            float hx = __bfloat162float(__float2bfloat16_rn(v.x));
            float hy = __bfloat162float(__float2bfloat16_rn(v.y));
            float hz = __bfloat162float(__float2bfloat16_rn(v.z));
            float hw = __bfloat162float(__float2bfloat16_rn(v.w));
            uint2 hi = make_uint2(pkbf(v.x, v.y), pkbf(v.z, v.w));
            uint2 lo = make_uint2(pkbf(v.x - hx, v.y - hy), pkbf(v.z - hz, v.w - hw));
            char* arow = sm + AOFF + row * 512;
            int ch = c4 >> 1, off8 = (c4 & 1) * 8, sw = row & 7;
            *(uint2*)(arow + ((ch ^ sw) << 4) + off8) = hi;
            *(uint2*)(arow + (((16 + ch) ^ sw) << 4) + off8) = lo;
        }
    }
    fillW(sm + WOFF, 0, tid);
    __syncthreads();

    float acc[2][4][4];

    // ======== Q gemm -> bf16 a-frags in registers (bias+scale folded) ========
    gemm32(smA, smW, m0, n0, lane, acc);
    u32 qh[2][2][4], ql[2][2][4];
#pragma unroll
    for (int mt = 0; mt < 2; ++mt)
#pragma unroll
        for (int nf = 0; nf < 4; ++nf) {
            int c = n0 + nf * 8 + 2 * (lane & 3);
            float2 b2 = __ldg((const float2*)(bq + c));
            float q0 = (acc[mt][nf][0] + b2.x) * QSCALE;
            float q1 = (acc[mt][nf][1] + b2.y) * QSCALE;
            float q2 = (acc[mt][nf][2] + b2.x) * QSCALE;
            float q3 = (acc[mt][nf][3] + b2.y) * QSCALE;
            int ks = nf >> 1, o = (nf & 1) * 2;
            qh[mt][ks][o] = pkbf(q0, q1);
            qh[mt][ks][o + 1] = pkbf(q2, q3);
            ql[mt][ks][o] = pkbf_lo(q0, q1, qh[mt][ks][o]);
            ql[mt][ks][o + 1] = pkbf_lo(q2, q3, qh[mt][ks][o + 1]);
        }
    __syncthreads();          // done reading Wq
    fillW(sm + WOFF, 1, tid); // Wk
    __syncthreads();

    // ======== K gemm -> score B-frags in registers (+bk) ========
    gemm32(smA, smW, m0, n0, lane, acc);
    u32 kbh[2][2][4], kbl[2][2][4];
#pragma unroll
    for (int mt = 0; mt < 2; ++mt)
#pragma unroll
        for (int nf = 0; nf < 4; ++nf) {
            int c = n0 + nf * 8 + 2 * (lane & 3);
            float2 b2 = __ldg((const float2*)(bk + c));
            float v0 = acc[mt][nf][0] + b2.x, v1 = acc[mt][nf][1] + b2.y;
            float v2 = acc[mt][nf][2] + b2.x, v3 = acc[mt][nf][3] + b2.y;
            kbh[mt][0][nf] = pkbf(v0, v1);
            kbl[mt][0][nf] = pkbf_lo(v0, v1, kbh[mt][0][nf]);
            kbh[mt][1][nf] = pkbf(v2, v3);
            kbl[mt][1][nf] = pkbf_lo(v2, v3, kbh[mt][1][nf]);
        }

    // scores: S[ms][2*mk+tb] = Q @ K^T (k = d, 2 k16 steps), 3-term
    float S[2][4][4];
#pragma unroll
    for (int mt = 0; mt < 2; ++mt)
#pragma unroll
        for (int nf = 0; nf < 4; ++nf)
#pragma unroll
            for (int c = 0; c < 4; ++c) S[mt][nf][c] = 0.f;
#pragma unroll
    for (int ks = 0; ks < 2; ++ks) {
#pragma unroll
        for (int ms = 0; ms < 2; ++ms)
#pragma unroll
            for (int mk = 0; mk < 2; ++mk)
#pragma unroll
                for (int tb = 0; tb < 2; ++tb)
                    mma16816(S[ms][2 * mk + tb], qh[ms][ks],
                             kbh[mk][tb][2 * ks], kbh[mk][tb][2 * ks + 1]);
#pragma unroll
        for (int ms = 0; ms < 2; ++ms)
#pragma unroll
            for (int mk = 0; mk < 2; ++mk)
#pragma unroll
                for (int tb = 0; tb < 2; ++tb)
                    mma16816(S[ms][2 * mk + tb], ql[ms][ks],
                             kbh[mk][tb][2 * ks], kbh[mk][tb][2 * ks + 1]);
#pragma unroll
        for (int ms = 0; ms < 2; ++ms)
#pragma unroll
            for (int mk = 0; mk < 2; ++mk)
#pragma unroll
                for (int tb = 0; tb < 2; ++tb)
                    mma16816(S[ms][2 * mk + tb], qh[ms][ks],
                             kbl[mk][tb][2 * ks], kbl[mk][tb][2 * ks + 1]);
    }

    // softmax over t (row groups of 4 lanes) -> P a-frags
    u32 ph[2][2][4], pl[2][2][4];
    {
        float mx[2][2], iv[2][2];
#pragma unroll
        for (int mt = 0; mt < 2; ++mt)
#pragma unroll
            for (int hf = 0; hf < 2; ++hf) {
                float m = -1e30f;
#pragma unroll
                for (int nf = 0; nf < 4; ++nf)
                    m = fmaxf(m, fmaxf(S[mt][nf][hf * 2], S[mt][nf][hf * 2 + 1]));
                m = fmaxf(m, __shfl_xor_sync(~0u, m, 1));
                m = fmaxf(m, __shfl_xor_sync(~0u, m, 2));
                mx[mt][hf] = m;
            }
#pragma unroll
        for (int mt = 0; mt < 2; ++mt)
#pragma unroll
            for (int nf = 0; nf < 4; ++nf) {
                S[mt][nf][0] = __expf(S[mt][nf][0] - mx[mt][0]);
                S[mt][nf][1] = __expf(S[mt][nf][1] - mx[mt][0]);
                S[mt][nf][2] = __expf(S[mt][nf][2] - mx[mt][1]);
                S[mt][nf][3] = __expf(S[mt][nf][3] - mx[mt][1]);
            }
#pragma unroll
        for (int mt = 0; mt < 2; ++mt)
#pragma unroll
            for (int hf = 0; hf < 2; ++hf) {
                float s = 0.f;
#pragma unroll
                for (int nf = 0; nf < 4; ++nf)
                    s += S[mt][nf][hf * 2] + S[mt][nf][hf * 2 + 1];
                s += __shfl_xor_sync(~0u, s, 1);
                s += __shfl_xor_sync(~0u, s, 2);
                iv[mt][hf] = 1.f / s;
            }
#pragma unroll
        for (int mt = 0; mt < 2; ++mt)
#pragma unroll
            for (int nf = 0; nf < 4; ++nf) {
                float p0 = S[mt][nf][0] * iv[mt][0];
                float p1 = S[mt][nf][1] * iv[mt][0];
                float p2 = S[mt][nf][2] * iv[mt][1];
                float p3 = S[mt][nf][3] * iv[mt][1];
                int ks = nf >> 1, o = (nf & 1) * 2;
                ph[mt][ks][o] = pkbf(p0, p1);
                ph[mt][ks][o + 1] = pkbf(p2, p3);
                pl[mt][ks][o] = pkbf_lo(p0, p1, ph[mt][ks][o]);
                pl[mt][ks][o + 1] = pkbf_lo(p2, p3, ph[mt][ks][o + 1]);
            }
    }
    __syncthreads();          // done reading Wk
    fillW(sm + WOFF, 2, tid); // Wv
    __syncthreads();

    // ======== V gemm -> ctx B-frags via movmatrix (+bv); ctx MMAs ========
    gemm32(smA, smW, m0, n0, lane, acc);
    u32 vbh[2][2][4], vbl[2][2][4];
#pragma unroll
    for (int mt = 0; mt < 2; ++mt)
#pragma unroll
        for (int nf = 0; nf < 4; ++nf) {
            int c = n0 + nf * 8 + 2 * (lane & 3);
            float2 b2 = __ldg((const float2*)(bv + c));
            float v0 = acc[mt][nf][0] + b2.x, v1 = acc[mt][nf][1] + b2.y;
            float v2 = acc[mt][nf][2] + b2.x, v3 = acc[mt][nf][3] + b2.y;
            u32 h01 = pkbf(v0, v1), l01 = pkbf_lo(v0, v1, h01);
            u32 h23 = pkbf(v2, v3), l23 = pkbf_lo(v2, v3, h23);
            vbh[mt][0][nf] = movm_t(h01);
            vbl[mt][0][nf] = movm_t(l01);
            vbh[mt][1][nf] = movm_t(h23);
            vbl[mt][1][nf] = movm_t(l23);
        }

    float C[2][4][4];
#pragma unroll
    for (int mt = 0; mt < 2; ++mt)
#pragma unroll
        for (int nf = 0; nf < 4; ++nf)
#pragma unroll
            for (int c = 0; c < 4; ++c) C[mt][nf][c] = 0.f;
#pragma unroll
    for (int kt = 0; kt < 2; ++kt) {
#pragma unroll
        for (int ms = 0; ms < 2; ++ms)
#pragma unroll
            for (int nf = 0; nf < 4; ++nf)
                mma16816(C[ms][nf], ph[ms][kt], vbh[kt][0][nf], vbh[kt][1][nf]);
#pragma unroll
        for (int ms = 0; ms < 2; ++ms)
#pragma unroll
            for (int nf = 0; nf < 4; ++nf)
                mma16816(C[ms][nf], pl[ms][kt], vbh[kt][0][nf], vbh[kt][1][nf]);
#pragma unroll
        for (int ms = 0; ms < 2; ++ms)
#pragma unroll
            for (int nf = 0; nf < 4; ++nf)
                mma16816(C[ms][nf], ph[ms][kt], vbl[kt][0][nf], vbl[kt][1][nf]);
    }

    __syncthreads();          // all warps done reading A (V gemm) and Wv
    store_split(sm + AOFF, C, m0, n0, lane);   // ctx -> A tile
    fillW(sm + WOFF, 3, tid);                  // Wo
    __syncthreads();

    // ======== out projection + epilogue ========
    gemm32(smA, smW, m0, n0, lane, acc);

    {
        float s1[2][2] = {{0.f, 0.f}, {0.f, 0.f}};
        float s2[2][2] = {{0.f, 0.f}, {0.f, 0.f}};
#pragma unroll
        for (int mt = 0; mt < 2; ++mt) {
            int r = m0 + mt * 16 + (lane >> 2);
#pragma unroll
            for (int nf = 0; nf < 4; ++nf) {
                int c = n0 + nf * 8 + 2 * (lane & 3);
                float2 b2 = __ldg((const float2*)(bo + c));
                float2 xa = __ldg((const float2*)(inputs + tbase + (size_t)r * 128 + c));
                float2 xb = __ldg((const float2*)(inputs + tbase + (size_t)(r + 8) * 128 + c));
                acc[mt][nf][0] += b2.x + xa.x; acc[mt][nf][1] += b2.y + xa.y;
                acc[mt][nf][2] += b2.x + xb.x; acc[mt][nf][3] += b2.y + xb.y;
                s1[mt][0] += acc[mt][nf][0] + acc[mt][nf][1];
                s2[mt][0] += acc[mt][nf][0] * acc[mt][nf][0] + acc[mt][nf][1] * acc[mt][nf][1];
                s1[mt][1] += acc[mt][nf][2] + acc[mt][nf][3];
                s2[mt][1] += acc[mt][nf][2] * acc[mt][nf][2] + acc[mt][nf][3] * acc[mt][nf][3];
            }
        }
#pragma unroll
        for (int mt = 0; mt < 2; ++mt)
#pragma unroll
            for (int hf = 0; hf < 2; ++hf) {
                s1[mt][hf] += __shfl_xor_sync(~0u, s1[mt][hf], 1);
                s1[mt][hf] += __shfl_xor_sync(~0u, s1[mt][hf], 2);
                s2[mt][hf] += __shfl_xor_sync(~0u, s2[mt][hf], 1);
                s2[mt][hf] += __shfl_xor_sync(~0u, s2[mt][hf], 2);
            }
        float2* part = (float2*)(sm + POFF);
        if ((lane & 3) == 0) {
#pragma unroll
            for (int mt = 0; mt < 2; ++mt) {
                int r = m0 + mt * 16 + (lane >> 2);
                part[r * 4 + h] = make_float2(s1[mt][0], s2[mt][0]);
                part[(r + 8) * 4 + h] = make_float2(s1[mt][1], s2[mt][1]);
            }
        }
        __syncthreads();
        float mu[2][2], rs[2][2];
#pragma unroll
        for (int mt = 0; mt < 2; ++mt)
#pragma unroll
            for (int hf = 0; hf < 2; ++hf) {
                int r = m0 + mt * 16 + (lane >> 2) + hf * 8;
                float2 p0 = part[r * 4 + 0], p1 = part[r * 4 + 1];
                float2 p2 = part[r * 4 + 2], p3 = part[r * 4 + 3];
                float S1 = p0.x + p1.x + p2.x + p3.x;
                float S2 = p0.y + p1.y + p2.y + p3.y;
                float m = S1 * (1.f / 128.f);
                float v = S2 * (1.f / 128.f) - m * m;
                mu[mt][hf] = m;
                rs[mt][hf] = rsqrtf(v + 1e-5f);
            }
#pragma unroll
        for (int mt = 0; mt < 2; ++mt) {
            int r = m0 + mt * 16 + (lane >> 2);
#pragma unroll
            for (int nf = 0; nf < 4; ++nf) {
                int c = n0 + nf * 8 + 2 * (lane & 3);
                float2 g2 = __ldg((const float2*)(gamma + c));
                float2 e2 = __ldg((const float2*)(beta + c));
                float2 o1, o2;
                o1.x = (acc[mt][nf][0] - mu[mt][0]) * rs[mt][0] * g2.x + e2.x;
                o1.y = (acc[mt][nf][1] - mu[mt][0]) * rs[mt][0] * g2.y + e2.y;
                o2.x = (acc[mt][nf][2] - mu[mt][1]) * rs[mt][1] * g2.x + e2.x;
                o2.y = (acc[mt][nf][3] - mu[mt][1]) * rs[mt][1] * g2.y + e2.y;
                *(float2*)(outp + tbase + (size_t)r * 128 + c) = o1;
                *(float2*)(outp + tbase + (size_t)(r + 8) * 128 + c) = o2;
            }
        }
    }
}

extern "C" void kernel_launch(void* const* d_in, const int* in_sizes, int n_in,
                              void* d_out, int out_size) {
    const float* inputs = (const float*)d_in[0];
    const float* Wq = (const float*)d_in[1];
    const float* bq = (const float*)d_in[2];
    const float* Wk = (const float*)d_in[3];
    const float* bk = (const float*)d_in[4];
    const float* Wv = (const float*)d_in[5];
    const float* bv = (const float*)d_in[6];
    const float* Wo = (const float*)d_in[7];
    const float* bo = (const float*)d_in[8];
    const float* gamma = (const float*)d_in[9];
    const float* beta  = (const float*)d_in[10];
    float* outp = (float*)d_out;

    prep_split<<<256, 256>>>(Wq, Wk, Wv, Wo);

    int grid = in_sizes[0] / 8192;   // 64 rows * 128 cols per CTA
    cudaFuncSetAttribute(fused_attn_fa,
                         cudaFuncAttributeMaxDynamicSharedMemorySize, SMEM_BYTES);
    fused_attn_fa<<<grid, NT, SMEM_BYTES>>>(inputs, bq, bk, bv, bo, gamma, beta, outp);
}

// round 13
// speedup vs baseline: 1.3925x; 1.3925x over previous
#include <cuda_runtime.h>
#include <cuda_fp16.h>
#include <cstdint>

// Fused SelfAttention, tensor-core HMMA (mma.sync f16, fp32 accum).
// E=128, S=32, H=4, D=32. CTA = 64 rows (2 batches), 256 threads, grid 8192.
// Warp w -> tile (m0=(w>>2)*32, n0=(w&3)*32) == attention block (batch, head).
// R12 numeric scheme: A (x / ctx) quantized to ONE fp16 value; W split fp16
// hi+lo. GEMM C = Ahi@Whi + Ahi@Wlo (2 terms). Attention q/k/v/p fp16, 1-term.
// Expected rel_err ~3e-4 (fp16 quantization), vs threshold 1e-3.
//
// SMEM:
//   A @0     : fp16 [64][128], 256B rows, 16B-chunk xor swizzle.          16KB
//   W @16384 : fp16 [128][256] (hi|lo), 512B rows, swizzled weight image. 64KB
//   LN partials @81920 : float2[64][4].                                    2KB

typedef unsigned int u32;

#define NT 256
#define AOFF 0
#define WOFF 16384
#define POFF 81920
#define SMEM_BYTES 83968
#define QSCALE 0.17677669529663687f

__device__ __align__(16) unsigned char g_Wpk[262144];

// ---------------- prep: split W into fp16 hi/lo swizzled smem images ----------
__global__ void prep_split(const float* __restrict__ Wq, const float* __restrict__ Wk,
                           const float* __restrict__ Wv, const float* __restrict__ Wo) {
    int id = blockIdx.x * blockDim.x + threadIdx.x;   // u32 words
    const float* W = (id < 16384) ? Wq : (id < 32768) ? Wk : (id < 49152) ? Wv : Wo;
    int rem = id & 16383;
    int f = rem >> 7;
    int w = rem & 127;
    int pc = w >> 2, j = w & 3;
    int lc = pc ^ (f & 7);
    int k0 = lc * 8 + j * 2;
    __half v[2];
#pragma unroll
    for (int i = 0; i < 2; ++i) {
        int kc = k0 + i;
        if (kc < 128) {
            v[i] = __float2half_rn(W[f * 128 + kc]);
        } else {
            float x = W[f * 128 + (kc - 128)];
            __half h = __float2half_rn(x);
            v[i] = __float2half_rn(x - __half2float(h));
        }
    }
    __half2 p = __halves2half2(v[0], v[1]);
    ((u32*)g_Wpk)[id] = *(u32*)&p;
}

// ---------------- helpers ----------------
__device__ __forceinline__ u32 s2u(const void* p) {
    u32 a;
    asm("{ .reg .u64 t; cvta.to.shared.u64 t, %1; cvt.u32.u64 %0, t; }" : "=r"(a) : "l"(p));
    return a;
}
__device__ __forceinline__ void ldsm4(u32* r, u32 a) {
    asm volatile("ldmatrix.sync.aligned.m8n8.x4.shared.b16 {%0,%1,%2,%3}, [%4];"
                 : "=r"(r[0]), "=r"(r[1]), "=r"(r[2]), "=r"(r[3]) : "r"(a));
}
__device__ __forceinline__ u32 movm_t(u32 s) {
    u32 d;
    asm("movmatrix.sync.aligned.m8n8.trans.b16 %0, %1;" : "=r"(d) : "r"(s));
    return d;
}
__device__ __forceinline__ void mma16816(float* c, const u32* a, u32 b0, u32 b1) {
    asm volatile(
        "mma.sync.aligned.m16n8k16.row.col.f32.f16.f16.f32 "
        "{%0,%1,%2,%3}, {%4,%5,%6,%7}, {%8,%9}, {%0,%1,%2,%3};"
        : "+f"(c[0]), "+f"(c[1]), "+f"(c[2]), "+f"(c[3])
        : "r"(a[0]), "r"(a[1]), "r"(a[2]), "r"(a[3]), "r"(b0), "r"(b1));
}
__device__ __forceinline__ u32 pkhf(float a, float b) {
    __half2 t = __halves2half2(__float2half_rn(a), __float2half_rn(b));
    return *(u32*)&t;
}

// C[m0:+32][n0:+32] = A(64x128 fp16) @ W^T(128x128 fp16 hi+lo), 2-term.
__device__ __forceinline__ void gemm32(u32 smA, u32 smW, int m0, int n0, int lane,
                                       float acc[2][4][4]) {
    u32 aRow[2]; int asw[2];
#pragma unroll
    for (int mt = 0; mt < 2; ++mt) {
        int ar = m0 + mt * 16 + (lane & 7) + ((lane & 8) ? 8 : 0);
        aRow[mt] = smA + ar * 256; asw[mt] = ar & 7;
    }
    const int acs = lane >> 4;
    u32 bRow[2]; int bsw[2];
#pragma unroll
    for (int ng = 0; ng < 2; ++ng) {
        int br = n0 + ng * 16 + (lane & 7) + ((lane & 16) ? 8 : 0);
        bRow[ng] = smW + br * 512; bsw[ng] = br & 7;
    }
    const int bcs = (lane >> 3) & 1;
#pragma unroll
    for (int mt = 0; mt < 2; ++mt)
#pragma unroll
        for (int nf = 0; nf < 4; ++nf)
#pragma unroll
            for (int c = 0; c < 4; ++c) acc[mt][nf][c] = 0.f;

#pragma unroll
    for (int j = 0; j < 8; ++j) {
        const int ach = 2 * j + acs, bch = 2 * j + bcs;
        u32 ah[2][4], bh[2][4], bl[2][4];
#pragma unroll
        for (int mt = 0; mt < 2; ++mt)
            ldsm4(ah[mt], aRow[mt] + ((ach ^ asw[mt]) << 4));
#pragma unroll
        for (int ng = 0; ng < 2; ++ng) {
            ldsm4(bh[ng], bRow[ng] + ((bch ^ bsw[ng]) << 4));
            ldsm4(bl[ng], bRow[ng] + (((16 + bch) ^ bsw[ng]) << 4));
        }
#pragma unroll
        for (int mt = 0; mt < 2; ++mt)
#pragma unroll
            for (int ng = 0; ng < 2; ++ng) {
                mma16816(acc[mt][2 * ng],     ah[mt], bh[ng][0], bh[ng][1]);
                mma16816(acc[mt][2 * ng + 1], ah[mt], bh[ng][2], bh[ng][3]);
            }
#pragma unroll
        for (int mt = 0; mt < 2; ++mt)
#pragma unroll
            for (int ng = 0; ng < 2; ++ng) {
                mma16816(acc[mt][2 * ng],     ah[mt], bl[ng][0], bl[ng][1]);
                mma16816(acc[mt][2 * ng + 1], ah[mt], bl[ng][2], bl[ng][3]);
            }
    }
}

// c-frags -> fp16 into the A-style [64][128] image (ctx writeback).
__device__ __forceinline__ void store_ctx(char* dst, const float acc[2][4][4],
                                          int m0, int n0, int lane) {
#pragma unroll
    for (int mt = 0; mt < 2; ++mt) {
        int r = m0 + mt * 16 + (lane >> 2);
        char* row0 = dst + r * 256;
        char* row1 = dst + (r + 8) * 256;
        int sw = r & 7;
#pragma unroll
        for (int nf = 0; nf < 4; ++nf) {
            int c = n0 + nf * 8 + 2 * (lane & 3);
            u32 h01 = pkhf(acc[mt][nf][0], acc[mt][nf][1]);
            u32 h23 = pkhf(acc[mt][nf][2], acc[mt][nf][3]);
            int ch = c >> 3, bo_ = (c & 7) * 2;
            *(u32*)(row0 + ((ch ^ sw) << 4) + bo_) = h01;
            *(u32*)(row1 + ((ch ^ sw) << 4) + bo_) = h23;
        }
    }
}

__device__ __forceinline__ void fillW(char* dstW, int g, int tid) {
    const uint4* src = (const uint4*)g_Wpk + g * 4096;
    uint4* dst = (uint4*)dstW;
#pragma unroll
    for (int p = 0; p < 16; ++p) dst[p * NT + tid] = __ldg(src + p * NT + tid);
}

// ---------------- main kernel ----------------
__global__ void __launch_bounds__(NT, 2)
fused_attn_fa(const float* __restrict__ inputs,
              const float* __restrict__ bq, const float* __restrict__ bk,
              const float* __restrict__ bv, const float* __restrict__ bo,
              const float* __restrict__ gamma, const float* __restrict__ beta,
              float* __restrict__ outp)
{
    extern __shared__ char sm[];
    const int tid = threadIdx.x;
    const int lane = tid & 31;
    const int warp = tid >> 5;
    const u32 smb = s2u(sm);
    const u32 smA = smb + AOFF, smW = smb + WOFF;
    const int m0 = (warp >> 2) * 32;    // batch block (rows): 0 or 32
    const int n0 = (warp & 3) * 32;     // head block (cols)
    const int h = warp & 3;
    const size_t tbase = (size_t)blockIdx.x * 8192;

    // ---- fill A (x -> fp16) + Wq ----
    {
        const float4* gx = (const float4*)(inputs + tbase);
#pragma unroll
        for (int p = 0; p < 8; ++p) {
            int e = p * NT + tid;
            int row = e >> 5, c4 = e & 31;
            float4 v = __ldg(gx + e);
            uint2 hi = make_uint2(pkhf(v.x, v.y), pkhf(v.z, v.w));
            char* arow = sm + AOFF + row * 256;
            int ch = c4 >> 1, off8 = (c4 & 1) * 8, sw = row & 7;
            *(uint2*)(arow + ((ch ^ sw) << 4) + off8) = hi;
        }
    }
    fillW(sm + WOFF, 0, tid);
    __syncthreads();

    float acc[2][4][4];

    // ======== Q gemm -> fp16 a-frags in registers (bias+scale folded) ========
    gemm32(smA, smW, m0, n0, lane, acc);
    u32 qh[2][2][4];
#pragma unroll
    for (int mt = 0; mt < 2; ++mt)
#pragma unroll
        for (int nf = 0; nf < 4; ++nf) {
            int c = n0 + nf * 8 + 2 * (lane & 3);
            float2 b2 = __ldg((const float2*)(bq + c));
            float q0 = (acc[mt][nf][0] + b2.x) * QSCALE;
            float q1 = (acc[mt][nf][1] + b2.y) * QSCALE;
            float q2 = (acc[mt][nf][2] + b2.x) * QSCALE;
            float q3 = (acc[mt][nf][3] + b2.y) * QSCALE;
            int ks = nf >> 1, o = (nf & 1) * 2;
            qh[mt][ks][o] = pkhf(q0, q1);
            qh[mt][ks][o + 1] = pkhf(q2, q3);
        }
    __syncthreads();          // done reading Wq
    fillW(sm + WOFF, 1, tid); // Wk
    __syncthreads();

    // ======== K gemm -> score B-frags in registers (+bk, fp16) ========
    gemm32(smA, smW, m0, n0, lane, acc);
    u32 kbh[2][2][4];
#pragma unroll
    for (int mt = 0; mt < 2; ++mt)
#pragma unroll
        for (int nf = 0; nf < 4; ++nf) {
            int c = n0 + nf * 8 + 2 * (lane & 3);
            float2 b2 = __ldg((const float2*)(bk + c));
            kbh[mt][0][nf] = pkhf(acc[mt][nf][0] + b2.x, acc[mt][nf][1] + b2.y);
            kbh[mt][1][nf] = pkhf(acc[mt][nf][2] + b2.x, acc[mt][nf][3] + b2.y);
        }

    // scores: S[ms][2*mk+tb] = Q @ K^T (k = d, 2 k16 steps), 1-term
    float S[2][4][4];
#pragma unroll
    for (int mt = 0; mt < 2; ++mt)
#pragma unroll
        for (int nf = 0; nf < 4; ++nf)
#pragma unroll
            for (int c = 0; c < 4; ++c) S[mt][nf][c] = 0.f;
#pragma unroll
    for (int ks = 0; ks < 2; ++ks)
#pragma unroll
        for (int ms = 0; ms < 2; ++ms)
#pragma unroll
            for (int mk = 0; mk < 2; ++mk)
#pragma unroll
                for (int tb = 0; tb < 2; ++tb)
                    mma16816(S[ms][2 * mk + tb], qh[ms][ks],
                             kbh[mk][tb][2 * ks], kbh[mk][tb][2 * ks + 1]);

    // softmax over t (row groups of 4 lanes) -> P a-frags (fp16)
    u32 ph[2][2][4];
    {
        float mx[2][2], iv[2][2];
#pragma unroll
        for (int mt = 0; mt < 2; ++mt)
#pragma unroll
            for (int hf = 0; hf < 2; ++hf) {
                float m = -1e30f;
#pragma unroll
                for (int nf = 0; nf < 4; ++nf)
                    m = fmaxf(m, fmaxf(S[mt][nf][hf * 2], S[mt][nf][hf * 2 + 1]));
                m = fmaxf(m, __shfl_xor_sync(~0u, m, 1));
                m = fmaxf(m, __shfl_xor_sync(~0u, m, 2));
                mx[mt][hf] = m;
            }
#pragma unroll
        for (int mt = 0; mt < 2; ++mt)
#pragma unroll
            for (int nf = 0; nf < 4; ++nf) {
                S[mt][nf][0] = __expf(S[mt][nf][0] - mx[mt][0]);
                S[mt][nf][1] = __expf(S[mt][nf][1] - mx[mt][0]);
                S[mt][nf][2] = __expf(S[mt][nf][2] - mx[mt][1]);
                S[mt][nf][3] = __expf(S[mt][nf][3] - mx[mt][1]);
            }
#pragma unroll
        for (int mt = 0; mt < 2; ++mt)
#pragma unroll
            for (int hf = 0; hf < 2; ++hf) {
                float s = 0.f;
#pragma unroll
                for (int nf = 0; nf < 4; ++nf)
                    s += S[mt][nf][hf * 2] + S[mt][nf][hf * 2 + 1];
                s += __shfl_xor_sync(~0u, s, 1);
                s += __shfl_xor_sync(~0u, s, 2);
                iv[mt][hf] = 1.f / s;
            }
#pragma unroll
        for (int mt = 0; mt < 2; ++mt)
#pragma unroll
            for (int nf = 0; nf < 4; ++nf) {
                float p0 = S[mt][nf][0] * iv[mt][0];
                float p1 = S[mt][nf][1] * iv[mt][0];
                float p2 = S[mt][nf][2] * iv[mt][1];
                float p3 = S[mt][nf][3] * iv[mt][1];
                int ks = nf >> 1, o = (nf & 1) * 2;
                ph[mt][ks][o] = pkhf(p0, p1);
                ph[mt][ks][o + 1] = pkhf(p2, p3);
            }
    }
    __syncthreads();          // done reading Wk
    fillW(sm + WOFF, 2, tid); // Wv
    __syncthreads();

    // ======== V gemm -> ctx B-frags via movmatrix (+bv, fp16); ctx MMAs ========
    gemm32(smA, smW, m0, n0, lane, acc);
    u32 vbh[2][2][4];
#pragma unroll
    for (int mt = 0; mt < 2; ++mt)
#pragma unroll
        for (int nf = 0; nf < 4; ++nf) {
            int c = n0 + nf * 8 + 2 * (lane & 3);
            float2 b2 = __ldg((const float2*)(bv + c));
            u32 h01 = pkhf(acc[mt][nf][0] + b2.x, acc[mt][nf][1] + b2.y);
            u32 h23 = pkhf(acc[mt][nf][2] + b2.x, acc[mt][nf][3] + b2.y);
            vbh[mt][0][nf] = movm_t(h01);
            vbh[mt][1][nf] = movm_t(h23);
        }

    float C[2][4][4];
#pragma unroll
    for (int mt = 0; mt < 2; ++mt)
#pragma unroll
        for (int nf = 0; nf < 4; ++nf)
#pragma unroll
            for (int c = 0; c < 4; ++c) C[mt][nf][c] = 0.f;
#pragma unroll
    for (int kt = 0; kt < 2; ++kt)
#pragma unroll
        for (int ms = 0; ms < 2; ++ms)
#pragma unroll
            for (int nf = 0; nf < 4; ++nf)
                mma16816(C[ms][nf], ph[ms][kt], vbh[kt][0][nf], vbh[kt][1][nf]);

    __syncthreads();          // all warps done reading A (V gemm) and Wv
    store_ctx(sm + AOFF, C, m0, n0, lane);     // ctx -> A tile (fp16)
    fillW(sm + WOFF, 3, tid);                  // Wo
    __syncthreads();

    // ======== out projection + epilogue ========
    gemm32(smA, smW, m0, n0, lane, acc);

    {
        float s1[2][2] = {{0.f, 0.f}, {0.f, 0.f}};
        float s2[2][2] = {{0.f, 0.f}, {0.f, 0.f}};
#pragma unroll
        for (int mt = 0; mt < 2; ++mt) {
            int r = m0 + mt * 16 + (lane >> 2);
#pragma unroll
            for (int nf = 0; nf < 4; ++nf) {
                int c = n0 + nf * 8 + 2 * (lane & 3);
                float2 b2 = __ldg((const float2*)(bo + c));
                float2 xa = __ldg((const float2*)(inputs + tbase + (size_t)r * 128 + c));
                float2 xb = __ldg((const float2*)(inputs + tbase + (size_t)(r + 8) * 128 + c));
                acc[mt][nf][0] += b2.x + xa.x; acc[mt][nf][1] += b2.y + xa.y;
                acc[mt][nf][2] += b2.x + xb.x; acc[mt][nf][3] += b2.y + xb.y;
                s1[mt][0] += acc[mt][nf][0] + acc[mt][nf][1];
                s2[mt][0] += acc[mt][nf][0] * acc[mt][nf][0] + acc[mt][nf][1] * acc[mt][nf][1];
                s1[mt][1] += acc[mt][nf][2] + acc[mt][nf][3];
                s2[mt][1] += acc[mt][nf][2] * acc[mt][nf][2] + acc[mt][nf][3] * acc[mt][nf][3];
            }
        }
#pragma unroll
        for (int mt = 0; mt < 2; ++mt)
#pragma unroll
            for (int hf = 0; hf < 2; ++hf) {
                s1[mt][hf] += __shfl_xor_sync(~0u, s1[mt][hf], 1);
                s1[mt][hf] += __shfl_xor_sync(~0u, s1[mt][hf], 2);
                s2[mt][hf] += __shfl_xor_sync(~0u, s2[mt][hf], 1);
                s2[mt][hf] += __shfl_xor_sync(~0u, s2[mt][hf], 2);
            }
        float2* part = (float2*)(sm + POFF);
        if ((lane & 3) == 0) {
#pragma unroll
            for (int mt = 0; mt < 2; ++mt) {
                int r = m0 + mt * 16 + (lane >> 2);
                part[r * 4 + h] = make_float2(s1[mt][0], s2[mt][0]);
                part[(r + 8) * 4 + h] = make_float2(s1[mt][1], s2[mt][1]);
            }
        }
        __syncthreads();
        float mu[2][2], rs[2][2];
#pragma unroll
        for (int mt = 0; mt < 2; ++mt)
#pragma unroll
            for (int hf = 0; hf < 2; ++hf) {
                int r = m0 + mt * 16 + (lane >> 2) + hf * 8;
                float2 p0 = part[r * 4 + 0], p1 = part[r * 4 + 1];
                float2 p2 = part[r * 4 + 2], p3 = part[r * 4 + 3];
                float S1 = p0.x + p1.x + p2.x + p3.x;
                float S2 = p0.y + p1.y + p2.y + p3.y;
                float m = S1 * (1.f / 128.f);
                float v = S2 * (1.f / 128.f) - m * m;
                mu[mt][hf] = m;
                rs[mt][hf] = rsqrtf(v + 1e-5f);
            }
#pragma unroll
        for (int mt = 0; mt < 2; ++mt) {
            int r = m0 + mt * 16 + (lane >> 2);
#pragma unroll
            for (int nf = 0; nf < 4; ++nf) {
                int c = n0 + nf * 8 + 2 * (lane & 3);
                float2 g2 = __ldg((const float2*)(gamma + c));
                float2 e2 = __ldg((const float2*)(beta + c));
                float2 o1, o2;
                o1.x = (acc[mt][nf][0] - mu[mt][0]) * rs[mt][0] * g2.x + e2.x;
                o1.y = (acc[mt][nf][1] - mu[mt][0]) * rs[mt][0] * g2.y + e2.y;
                o2.x = (acc[mt][nf][2] - mu[mt][1]) * rs[mt][1] * g2.x + e2.x;
                o2.y = (acc[mt][nf][3] - mu[mt][1]) * rs[mt][1] * g2.y + e2.y;
                *(float2*)(outp + tbase + (size_t)r * 128 + c) = o1;
                *(float2*)(outp + tbase + (size_t)(r + 8) * 128 + c) = o2;
            }
        }
    }
}

extern "C" void kernel_launch(void* const* d_in, const int* in_sizes, int n_in,
                              void* d_out, int out_size) {
    const float* inputs = (const float*)d_in[0];
    const float* Wq = (const float*)d_in[1];
    const float* bq = (const float*)d_in[2];
    const float* Wk = (const float*)d_in[3];
    const float* bk = (const float*)d_in[4];
    const float* Wv = (const float*)d_in[5];
    const float* bv = (const float*)d_in[6];
    const float* Wo = (const float*)d_in[7];
    const float* bo = (const float*)d_in[8];
    const float* gamma = (const float*)d_in[9];
    const float* beta  = (const float*)d_in[10];
    float* outp = (float*)d_out;

    prep_split<<<256, 256>>>(Wq, Wk, Wv, Wo);

    int grid = in_sizes[0] / 8192;   // 64 rows * 128 cols per CTA
    cudaFuncSetAttribute(fused_attn_fa,
                         cudaFuncAttributeMaxDynamicSharedMemorySize, SMEM_BYTES);
    fused_attn_fa<<<grid, NT, SMEM_BYTES>>>(inputs, bq, bk, bv, bo, gamma, beta, outp);
}

// round 15
// speedup vs baseline: 2.0342x; 1.4608x over previous
#include <cuda_runtime.h>
#include <cuda_fp16.h>
#include <cstdint>

// Fused SelfAttention, tensor-core HMMA (mma.sync f16, fp32 accum).
// E=128, S=32, H=4, D=32. CTA = 64 rows (2 batches), 256 threads, grid 8192.
// Warp w -> tile (m0=(w>>2)*32, n0=(w&3)*32) == attention block (batch, head).
// R14: same as R13 (1-term fp16 GEMMs, W single fp16) with the prep_split
// indexing bug fixed: 256B rows = 64 u32 words -> f = rem>>6, w = rem&63.
//
// SMEM:
//   A @0     : fp16 [64][128], 256B rows, 16B-chunk xor swizzle.  16KB
//   W @16384 : fp16 [128][128], 256B rows, swizzled weight image. 32KB
//   LN partials @49152 : float2[64][4].                            2KB

typedef unsigned int u32;

#define NT 256
#define AOFF 0
#define WOFF 16384
#define POFF 49152
#define SMEM_BYTES 51200
#define QSCALE 0.17677669529663687f

// 4 weights x 32KB swizzled fp16 image
__device__ __align__(16) unsigned char g_Wpk[131072];

// ---------------- prep: W -> fp16 swizzled smem images ----------------
__global__ void prep_split(const float* __restrict__ Wq, const float* __restrict__ Wk,
                           const float* __restrict__ Wv, const float* __restrict__ Wo) {
    int id = blockIdx.x * blockDim.x + threadIdx.x;   // 0..32767 u32 words
    const float* W = (id < 8192) ? Wq : (id < 16384) ? Wk : (id < 24576) ? Wv : Wo;
    int rem = id & 8191;
    int f = rem >> 6;          // row 0..127 (64 u32 words per 256B row)
    int w = rem & 63;          // u32 word within 256B row
    int pc = w >> 2, j = w & 3;   // 16B chunk 0..15, u32 within chunk
    int lc = pc ^ (f & 7);     // logical 16B chunk
    int k0 = lc * 8 + j * 2;   // logical fp16 col (0..127)
    __half2 p = __halves2half2(__float2half_rn(W[f * 128 + k0]),
                               __float2half_rn(W[f * 128 + k0 + 1]));
    ((u32*)g_Wpk)[id] = *(u32*)&p;
}

// ---------------- helpers ----------------
__device__ __forceinline__ u32 s2u(const void* p) {
    u32 a;
    asm("{ .reg .u64 t; cvta.to.shared.u64 t, %1; cvt.u32.u64 %0, t; }" : "=r"(a) : "l"(p));
    return a;
}
__device__ __forceinline__ void ldsm4(u32* r, u32 a) {
    asm volatile("ldmatrix.sync.aligned.m8n8.x4.shared.b16 {%0,%1,%2,%3}, [%4];"
                 : "=r"(r[0]), "=r"(r[1]), "=r"(r[2]), "=r"(r[3]) : "r"(a));
}
__device__ __forceinline__ u32 movm_t(u32 s) {
    u32 d;
    asm("movmatrix.sync.aligned.m8n8.trans.b16 %0, %1;" : "=r"(d) : "r"(s));
    return d;
}
__device__ __forceinline__ void mma16816(float* c, const u32* a, u32 b0, u32 b1) {
    asm volatile(
        "mma.sync.aligned.m16n8k16.row.col.f32.f16.f16.f32 "
        "{%0,%1,%2,%3}, {%4,%5,%6,%7}, {%8,%9}, {%0,%1,%2,%3};"
        : "+f"(c[0]), "+f"(c[1]), "+f"(c[2]), "+f"(c[3])
        : "r"(a[0]), "r"(a[1]), "r"(a[2]), "r"(a[3]), "r"(b0), "r"(b1));
}
__device__ __forceinline__ u32 pkhf(float a, float b) {
    __half2 t = __halves2half2(__float2half_rn(a), __float2half_rn(b));
    return *(u32*)&t;
}

// C[m0:+32][n0:+32] = A(64x128 fp16) @ W^T(128x128 fp16), 1-term.
__device__ __forceinline__ void gemm32(u32 smA, u32 smW, int m0, int n0, int lane,
                                       float acc[2][4][4]) {
    u32 aRow[2]; int asw[2];
#pragma unroll
    for (int mt = 0; mt < 2; ++mt) {
        int ar = m0 + mt * 16 + (lane & 7) + ((lane & 8) ? 8 : 0);
        aRow[mt] = smA + ar * 256; asw[mt] = ar & 7;
    }
    const int acs = lane >> 4;
    u32 bRow[2]; int bsw[2];
#pragma unroll
    for (int ng = 0; ng < 2; ++ng) {
        int br = n0 + ng * 16 + (lane & 7) + ((lane & 16) ? 8 : 0);
        bRow[ng] = smW + br * 256; bsw[ng] = br & 7;
    }
    const int bcs = (lane >> 3) & 1;
#pragma unroll
    for (int mt = 0; mt < 2; ++mt)
#pragma unroll
        for (int nf = 0; nf < 4; ++nf)
#pragma unroll
            for (int c = 0; c < 4; ++c) acc[mt][nf][c] = 0.f;

#pragma unroll
    for (int j = 0; j < 8; ++j) {
        const int ach = 2 * j + acs, bch = 2 * j + bcs;
        u32 ah[2][4], bh[2][4];
#pragma unroll
        for (int mt = 0; mt < 2; ++mt)
            ldsm4(ah[mt], aRow[mt] + ((ach ^ asw[mt]) << 4));
#pragma unroll
        for (int ng = 0; ng < 2; ++ng)
            ldsm4(bh[ng], bRow[ng] + ((bch ^ bsw[ng]) << 4));
#pragma unroll
        for (int mt = 0; mt < 2; ++mt)
#pragma unroll
            for (int ng = 0; ng < 2; ++ng) {
                mma16816(acc[mt][2 * ng],     ah[mt], bh[ng][0], bh[ng][1]);
                mma16816(acc[mt][2 * ng + 1], ah[mt], bh[ng][2], bh[ng][3]);
            }
    }
}

// c-frags -> fp16 into the A-style [64][128] image (ctx writeback).
__device__ __forceinline__ void store_ctx(char* dst, const float acc[2][4][4],
                                          int m0, int n0, int lane) {
#pragma unroll
    for (int mt = 0; mt < 2; ++mt) {
        int r = m0 + mt * 16 + (lane >> 2);
        char* row0 = dst + r * 256;
        char* row1 = dst + (r + 8) * 256;
        int sw = r & 7;
#pragma unroll
        for (int nf = 0; nf < 4; ++nf) {
            int c = n0 + nf * 8 + 2 * (lane & 3);
            u32 h01 = pkhf(acc[mt][nf][0], acc[mt][nf][1]);
            u32 h23 = pkhf(acc[mt][nf][2], acc[mt][nf][3]);
            int ch = c >> 3, bo_ = (c & 7) * 2;
            *(u32*)(row0 + ((ch ^ sw) << 4) + bo_) = h01;
            *(u32*)(row1 + ((ch ^ sw) << 4) + bo_) = h23;
        }
    }
}

__device__ __forceinline__ void fillW(char* dstW, int g, int tid) {
    const uint4* src = (const uint4*)g_Wpk + g * 2048;
    uint4* dst = (uint4*)dstW;
#pragma unroll
    for (int p = 0; p < 8; ++p) dst[p * NT + tid] = __ldg(src + p * NT + tid);
}

// ---------------- main kernel ----------------
__global__ void __launch_bounds__(NT, 2)
fused_attn_fa(const float* __restrict__ inputs,
              const float* __restrict__ bq, const float* __restrict__ bk,
              const float* __restrict__ bv, const float* __restrict__ bo,
              const float* __restrict__ gamma, const float* __restrict__ beta,
              float* __restrict__ outp)
{
    extern __shared__ char sm[];
    const int tid = threadIdx.x;
    const int lane = tid & 31;
    const int warp = tid >> 5;
    const u32 smb = s2u(sm);
    const u32 smA = smb + AOFF, smW = smb + WOFF;
    const int m0 = (warp >> 2) * 32;    // batch block (rows): 0 or 32
    const int n0 = (warp & 3) * 32;     // head block (cols)
    const int h = warp & 3;
    const size_t tbase = (size_t)blockIdx.x * 8192;

    // ---- fill A (x -> fp16) + Wq ----
    {
        const float4* gx = (const float4*)(inputs + tbase);
#pragma unroll
        for (int p = 0; p < 8; ++p) {
            int e = p * NT + tid;
            int row = e >> 5, c4 = e & 31;
            float4 v = __ldg(gx + e);
            uint2 hi = make_uint2(pkhf(v.x, v.y), pkhf(v.z, v.w));
            char* arow = sm + AOFF + row * 256;
            int ch = c4 >> 1, off8 = (c4 & 1) * 8, sw = row & 7;
            *(uint2*)(arow + ((ch ^ sw) << 4) + off8) = hi;
        }
    }
    fillW(sm + WOFF, 0, tid);
    __syncthreads();

    float acc[2][4][4];

    // ======== Q gemm -> fp16 a-frags in registers (bias+scale folded) ========
    gemm32(smA, smW, m0, n0, lane, acc);
    u32 qh[2][2][4];
#pragma unroll
    for (int mt = 0; mt < 2; ++mt)
#pragma unroll
        for (int nf = 0; nf < 4; ++nf) {
            int c = n0 + nf * 8 + 2 * (lane & 3);
            float2 b2 = __ldg((const float2*)(bq + c));
            float q0 = (acc[mt][nf][0] + b2.x) * QSCALE;
            float q1 = (acc[mt][nf][1] + b2.y) * QSCALE;
            float q2 = (acc[mt][nf][2] + b2.x) * QSCALE;
            float q3 = (acc[mt][nf][3] + b2.y) * QSCALE;
            int ks = nf >> 1, o = (nf & 1) * 2;
            qh[mt][ks][o] = pkhf(q0, q1);
            qh[mt][ks][o + 1] = pkhf(q2, q3);
        }
    __syncthreads();          // done reading Wq
    fillW(sm + WOFF, 1, tid); // Wk
    __syncthreads();

    // ======== K gemm -> score B-frags in registers (+bk, fp16) ========
    gemm32(smA, smW, m0, n0, lane, acc);
    u32 kbh[2][2][4];
#pragma unroll
    for (int mt = 0; mt < 2; ++mt)
#pragma unroll
        for (int nf = 0; nf < 4; ++nf) {
            int c = n0 + nf * 8 + 2 * (lane & 3);
            float2 b2 = __ldg((const float2*)(bk + c));
            kbh[mt][0][nf] = pkhf(acc[mt][nf][0] + b2.x, acc[mt][nf][1] + b2.y);
            kbh[mt][1][nf] = pkhf(acc[mt][nf][2] + b2.x, acc[mt][nf][3] + b2.y);
        }

    // scores: S[ms][2*mk+tb] = Q @ K^T (k = d, 2 k16 steps), 1-term
    float S[2][4][4];
#pragma unroll
    for (int mt = 0; mt < 2; ++mt)
#pragma unroll
        for (int nf = 0; nf < 4; ++nf)
#pragma unroll
            for (int c = 0; c < 4; ++c) S[mt][nf][c] = 0.f;
#pragma unroll
    for (int ks = 0; ks < 2; ++ks)
#pragma unroll
        for (int ms = 0; ms < 2; ++ms)
#pragma unroll
            for (int mk = 0; mk < 2; ++mk)
#pragma unroll
                for (int tb = 0; tb < 2; ++tb)
                    mma16816(S[ms][2 * mk + tb], qh[ms][ks],
                             kbh[mk][tb][2 * ks], kbh[mk][tb][2 * ks + 1]);

    // softmax over t (row groups of 4 lanes) -> P a-frags (fp16)
    u32 ph[2][2][4];
    {
        float mx[2][2], iv[2][2];
#pragma unroll
        for (int mt = 0; mt < 2; ++mt)
#pragma unroll
            for (int hf = 0; hf < 2; ++hf) {
                float m = -1e30f;
#pragma unroll
                for (int nf = 0; nf < 4; ++nf)
                    m = fmaxf(m, fmaxf(S[mt][nf][hf * 2], S[mt][nf][hf * 2 + 1]));
                m = fmaxf(m, __shfl_xor_sync(~0u, m, 1));
                m = fmaxf(m, __shfl_xor_sync(~0u, m, 2));
                mx[mt][hf] = m;
            }
#pragma unroll
        for (int mt = 0; mt < 2; ++mt)
#pragma unroll
            for (int nf = 0; nf < 4; ++nf) {
                S[mt][nf][0] = __expf(S[mt][nf][0] - mx[mt][0]);
                S[mt][nf][1] = __expf(S[mt][nf][1] - mx[mt][0]);
                S[mt][nf][2] = __expf(S[mt][nf][2] - mx[mt][1]);
                S[mt][nf][3] = __expf(S[mt][nf][3] - mx[mt][1]);
            }
#pragma unroll
        for (int mt = 0; mt < 2; ++mt)
#pragma unroll
            for (int hf = 0; hf < 2; ++hf) {
                float s = 0.f;
#pragma unroll
                for (int nf = 0; nf < 4; ++nf)
                    s += S[mt][nf][hf * 2] + S[mt][nf][hf * 2 + 1];
                s += __shfl_xor_sync(~0u, s, 1);
                s += __shfl_xor_sync(~0u, s, 2);
                iv[mt][hf] = 1.f / s;
            }
#pragma unroll
        for (int mt = 0; mt < 2; ++mt)
#pragma unroll
            for (int nf = 0; nf < 4; ++nf) {
                float p0 = S[mt][nf][0] * iv[mt][0];
                float p1 = S[mt][nf][1] * iv[mt][0];
                float p2 = S[mt][nf][2] * iv[mt][1];
                float p3 = S[mt][nf][3] * iv[mt][1];
                int ks = nf >> 1, o = (nf & 1) * 2;
                ph[mt][ks][o] = pkhf(p0, p1);
                ph[mt][ks][o + 1] = pkhf(p2, p3);
            }
    }
    __syncthreads();          // done reading Wk
    fillW(sm + WOFF, 2, tid); // Wv
    __syncthreads();

    // ======== V gemm -> ctx B-frags via movmatrix (+bv, fp16); ctx MMAs ========
    gemm32(smA, smW, m0, n0, lane, acc);
    u32 vbh[2][2][4];
#pragma unroll
    for (int mt = 0; mt < 2; ++mt)
#pragma unroll
        for (int nf = 0; nf < 4; ++nf) {
            int c = n0 + nf * 8 + 2 * (lane & 3);
            float2 b2 = __ldg((const float2*)(bv + c));
            u32 h01 = pkhf(acc[mt][nf][0] + b2.x, acc[mt][nf][1] + b2.y);
            u32 h23 = pkhf(acc[mt][nf][2] + b2.x, acc[mt][nf][3] + b2.y);
            vbh[mt][0][nf] = movm_t(h01);
            vbh[mt][1][nf] = movm_t(h23);
        }

    float C[2][4][4];
#pragma unroll
    for (int mt = 0; mt < 2; ++mt)
#pragma unroll
        for (int nf = 0; nf < 4; ++nf)
#pragma unroll
            for (int c = 0; c < 4; ++c) C[mt][nf][c] = 0.f;
#pragma unroll
    for (int kt = 0; kt < 2; ++kt)
#pragma unroll
        for (int ms = 0; ms < 2; ++ms)
#pragma unroll
            for (int nf = 0; nf < 4; ++nf)
                mma16816(C[ms][nf], ph[ms][kt], vbh[kt][0][nf], vbh[kt][1][nf]);

    __syncthreads();          // all warps done reading A (V gemm) and Wv
    store_ctx(sm + AOFF, C, m0, n0, lane);     // ctx -> A tile (fp16)
    fillW(sm + WOFF, 3, tid);                  // Wo
    __syncthreads();

    // ======== out projection + epilogue ========
    gemm32(smA, smW, m0, n0, lane, acc);

    {
        float s1[2][2] = {{0.f, 0.f}, {0.f, 0.f}};
        float s2[2][2] = {{0.f, 0.f}, {0.f, 0.f}};
#pragma unroll
        for (int mt = 0; mt < 2; ++mt) {
            int r = m0 + mt * 16 + (lane >> 2);
#pragma unroll
            for (int nf = 0; nf < 4; ++nf) {
                int c = n0 + nf * 8 + 2 * (lane & 3);
                float2 b2 = __ldg((const float2*)(bo + c));
                float2 xa = __ldg((const float2*)(inputs + tbase + (size_t)r * 128 + c));
                float2 xb = __ldg((const float2*)(inputs + tbase + (size_t)(r + 8) * 128 + c));
                acc[mt][nf][0] += b2.x + xa.x; acc[mt][nf][1] += b2.y + xa.y;
                acc[mt][nf][2] += b2.x + xb.x; acc[mt][nf][3] += b2.y + xb.y;
                s1[mt][0] += acc[mt][nf][0] + acc[mt][nf][1];
                s2[mt][0] += acc[mt][nf][0] * acc[mt][nf][0] + acc[mt][nf][1] * acc[mt][nf][1];
                s1[mt][1] += acc[mt][nf][2] + acc[mt][nf][3];
                s2[mt][1] += acc[mt][nf][2] * acc[mt][nf][2] + acc[mt][nf][3] * acc[mt][nf][3];
            }
        }
#pragma unroll
        for (int mt = 0; mt < 2; ++mt)
#pragma unroll
            for (int hf = 0; hf < 2; ++hf) {
                s1[mt][hf] += __shfl_xor_sync(~0u, s1[mt][hf], 1);
                s1[mt][hf] += __shfl_xor_sync(~0u, s1[mt][hf], 2);
                s2[mt][hf] += __shfl_xor_sync(~0u, s2[mt][hf], 1);
                s2[mt][hf] += __shfl_xor_sync(~0u, s2[mt][hf], 2);
            }
        float2* part = (float2*)(sm + POFF);
        if ((lane & 3) == 0) {
#pragma unroll
            for (int mt = 0; mt < 2; ++mt) {
                int r = m0 + mt * 16 + (lane >> 2);
                part[r * 4 + h] = make_float2(s1[mt][0], s2[mt][0]);
                part[(r + 8) * 4 + h] = make_float2(s1[mt][1], s2[mt][1]);
            }
        }
        __syncthreads();
        float mu[2][2], rs[2][2];
#pragma unroll
        for (int mt = 0; mt < 2; ++mt)
#pragma unroll
            for (int hf = 0; hf < 2; ++hf) {
                int r = m0 + mt * 16 + (lane >> 2) + hf * 8;
                float2 p0 = part[r * 4 + 0], p1 = part[r * 4 + 1];
                float2 p2 = part[r * 4 + 2], p3 = part[r * 4 + 3];
                float S1 = p0.x + p1.x + p2.x + p3.x;
                float S2 = p0.y + p1.y + p2.y + p3.y;
                float m = S1 * (1.f / 128.f);
                float v = S2 * (1.f / 128.f) - m * m;
                mu[mt][hf] = m;
                rs[mt][hf] = rsqrtf(v + 1e-5f);
            }
#pragma unroll
        for (int mt = 0; mt < 2; ++mt) {
            int r = m0 + mt * 16 + (lane >> 2);
#pragma unroll
            for (int nf = 0; nf < 4; ++nf) {
                int c = n0 + nf * 8 + 2 * (lane & 3);
                float2 g2 = __ldg((const float2*)(gamma + c));
                float2 e2 = __ldg((const float2*)(beta + c));
                float2 o1, o2;
                o1.x = (acc[mt][nf][0] - mu[mt][0]) * rs[mt][0] * g2.x + e2.x;
                o1.y = (acc[mt][nf][1] - mu[mt][0]) * rs[mt][0] * g2.y + e2.y;
                o2.x = (acc[mt][nf][2] - mu[mt][1]) * rs[mt][1] * g2.x + e2.x;
                o2.y = (acc[mt][nf][3] - mu[mt][1]) * rs[mt][1] * g2.y + e2.y;
                *(float2*)(outp + tbase + (size_t)r * 128 + c) = o1;
                *(float2*)(outp + tbase + (size_t)(r + 8) * 128 + c) = o2;
            }
        }
    }
}

extern "C" void kernel_launch(void* const* d_in, const int* in_sizes, int n_in,
                              void* d_out, int out_size) {
    const float* inputs = (const float*)d_in[0];
    const float* Wq = (const float*)d_in[1];
    const float* bq = (const float*)d_in[2];
    const float* Wk = (const float*)d_in[3];
    const float* bk = (const float*)d_in[4];
    const float* Wv = (const float*)d_in[5];
    const float* bv = (const float*)d_in[6];
    const float* Wo = (const float*)d_in[7];
    const float* bo = (const float*)d_in[8];
    const float* gamma = (const float*)d_in[9];
    const float* beta  = (const float*)d_in[10];
    float* outp = (float*)d_out;

    prep_split<<<128, 256>>>(Wq, Wk, Wv, Wo);

    int grid = in_sizes[0] / 8192;   // 64 rows * 128 cols per CTA
    cudaFuncSetAttribute(fused_attn_fa,
                         cudaFuncAttributeMaxDynamicSharedMemorySize, SMEM_BYTES);
    fused_attn_fa<<<grid, NT, SMEM_BYTES>>>(inputs, bq, bk, bv, bo, gamma, beta, outp);
}